// round 2
// baseline (speedup 1.0000x reference)
#include <cuda_runtime.h>
#include <cstdint>
#include <cstddef>

typedef unsigned long long ull;

#define BB 32
#define TT 1024
#define HH 512
#define GG 2048
#define NCTA 128

// ---------------- device scratch (allocations are forbidden) ----------------
__device__ __align__(16) float g_xp[(size_t)TT * GG * BB];   // 256 MB x_proj[t][g][b]
__device__ __align__(16) float g_hbuf[2][HH * BB];           // ping-pong h[k][b]
__device__ unsigned g_bar_count;
__device__ unsigned g_bar_phase;

// ---------------- f32x2 helpers (FFMA2 is PTX-only) ----------------
__device__ __forceinline__ ull ffma2(ull a, ull b, ull c) {
    ull d;
    asm("fma.rn.f32x2 %0, %1, %2, %3;" : "=l"(d) : "l"(a), "l"(b), "l"(c));
    return d;
}
__device__ __forceinline__ ull fadd2(ull a, ull b) {
    ull d;
    asm("add.rn.f32x2 %0, %1, %2;" : "=l"(d) : "l"(a), "l"(b));
    return d;
}
__device__ __forceinline__ ull pack2(float x, float y) {
    ull d;
    asm("mov.b64 %0, {%1, %2};" : "=l"(d) : "f"(x), "f"(y));
    return d;
}

__device__ __forceinline__ float sigm(float x) { return 1.0f / (1.0f + __expf(-x)); }

// ---------------- init: zero h buffers + barrier state ----------------
__global__ void init_kernel() {
    int i = blockIdx.x * blockDim.x + threadIdx.x;
    if (i < HH * BB) { g_hbuf[0][i] = 0.0f; g_hbuf[1][i] = 0.0f; }
    if (i == 0) { g_bar_count = 0; g_bar_phase = 0; }
}

// =========================================================================
// Kernel 1: x_proj[t][g][b] = sum_c src[b][t][c]*W_ih[g][c] + b_ih[g]+b_hh[g]
// grid (8, 256): 256 g x (4 t * 32 b = 128 n) per CTA, K chunks of 64.
// 512 threads, per-thread 8g x 8n, f32x2 accumulators over n-pairs.
// =========================================================================
#define WPITCH 68   // 64 + 4 pad (words)
#define XPITCH 132  // 128 + 4 pad (words), multiple of 4 for LDS.128

__global__ __launch_bounds__(512, 1) void xproj_kernel(
    const float* __restrict__ src, const float* __restrict__ Wih,
    const float* __restrict__ bih, const float* __restrict__ bhh)
{
    extern __shared__ float sm[];
    float* w_s = sm;                  // [256][WPITCH]
    float* x_s = sm + 256 * WPITCH;   // [64][XPITCH]  x transposed: [c][n]

    const int tid = threadIdx.x;
    const int g0  = blockIdx.x * 256;
    const int t0  = blockIdx.y * 4;
    const int ni  = tid & 15;    // n tile: ni*8 .. ni*8+7
    const int gi  = tid >> 4;    // g tile: gi*8 .. gi*8+7

    ull acc[32];
#pragma unroll
    for (int i = 0; i < 32; i++) acc[i] = 0ull;

    for (int kc = 0; kc < 8; kc++) {
        const int c0 = kc * 64;
        // stage W chunk [256 g][64 c]
#pragma unroll
        for (int i = 0; i < 8; i++) {
            int fq = tid + i * 512;            // 0..4095
            int g = fq >> 4, cq = fq & 15;
            float4 wv = *(const float4*)(Wih + (size_t)(g0 + g) * HH + c0 + cq * 4);
            *(float4*)(w_s + g * WPITCH + cq * 4) = wv;
        }
        // stage X chunk transposed to [c][n]; n fastest over lanes -> conflict-free STS
#pragma unroll
        for (int i = 0; i < 4; i++) {
            int fq = tid + i * 512;            // 0..2047
            int n = fq & 127, cq = fq >> 7;    // cq in [0,16)
            int b = n & 31, ti = n >> 5;
            float4 xv = *(const float4*)(src + ((size_t)b * TT + (t0 + ti)) * HH + c0 + cq * 4);
            x_s[(cq * 4 + 0) * XPITCH + n] = xv.x;
            x_s[(cq * 4 + 1) * XPITCH + n] = xv.y;
            x_s[(cq * 4 + 2) * XPITCH + n] = xv.z;
            x_s[(cq * 4 + 3) * XPITCH + n] = xv.w;
        }
        __syncthreads();

#pragma unroll 4
        for (int k = 0; k < 64; k++) {
            ulonglong2 xa = *(const ulonglong2*)(x_s + k * XPITCH + ni * 8);
            ulonglong2 xb = *(const ulonglong2*)(x_s + k * XPITCH + ni * 8 + 4);
            const float* wr = w_s + (gi * 8) * WPITCH + k;
#pragma unroll
            for (int i = 0; i < 8; i++) {
                float w = wr[i * WPITCH];
                ull w2 = pack2(w, w);
                acc[i * 4 + 0] = ffma2(xa.x, w2, acc[i * 4 + 0]);
                acc[i * 4 + 1] = ffma2(xa.y, w2, acc[i * 4 + 1]);
                acc[i * 4 + 2] = ffma2(xb.x, w2, acc[i * 4 + 2]);
                acc[i * 4 + 3] = ffma2(xb.y, w2, acc[i * 4 + 3]);
            }
        }
        __syncthreads();
    }

    // epilogue: add biases, store pairs to g_xp[t][g][b]
#pragma unroll
    for (int i = 0; i < 8; i++) {
        int g = g0 + gi * 8 + i;
        float bs = bih[g] + bhh[g];
        ull b2 = pack2(bs, bs);
#pragma unroll
        for (int p = 0; p < 4; p++) {
            int n = ni * 8 + 2 * p;
            int t = t0 + (n >> 5), b = n & 31;
            ull v = fadd2(acc[i * 4 + p], b2);
            *(ull*)(g_xp + ((size_t)t * GG + g) * BB + b) = v;
        }
    }
}

// =========================================================================
// Kernel 2: persistent LSTM recurrence. 128 CTAs x 256 threads.
// CTA owns h units [4*cta, 4*cta+4) -> 16 gate rows (4 gates x 4 units).
// Thread (rp = tid&7, kc = tid>>3): rows {rp, rp+8}, k in [kc*16, kc*16+16).
// W_hh slice pre-packed {w,w} in registers; h staged to swizzled smem.
// =========================================================================
#define RED_PITCH 34   // 32 + 2 pad (words), even -> 8B-aligned ull slots

__device__ __forceinline__ void gridbar(unsigned target) {
    __syncthreads();
    if (threadIdx.x == 0) {
        __threadfence();
        unsigned arrive = atomicAdd(&g_bar_count, 1u) + 1u;
        if (arrive == (unsigned)NCTA * target) {
            asm volatile("st.release.gpu.u32 [%0], %1;" :: "l"(&g_bar_phase), "r"(target) : "memory");
        } else {
            unsigned ph;
            do {
                asm volatile("ld.acquire.gpu.u32 %0, [%1];" : "=r"(ph) : "l"(&g_bar_phase) : "memory");
            } while (ph < target);
        }
    }
    __syncthreads();
}

__global__ __launch_bounds__(256, 1) void lstm_kernel(
    const int* __restrict__ lengths, const float* __restrict__ Whh,
    float* __restrict__ out)
{
    extern __shared__ float sm[];
    float* h_s = sm;                 // [512][32] swizzled, 64 KB
    float* red = sm + HH * BB;       // [32 kc][16 rows][RED_PITCH]
    float* ho  = red + 32 * 16 * RED_PITCH;  // [32 b][4 h]

    const int tid = threadIdx.x;
    const int cta = blockIdx.x;
    const int rp  = tid & 7;          // rows rp and rp+8
    const int kc  = tid >> 3;         // 0..31, k in [kc*16, kc*16+16)
    const int gateA = rp >> 2, hofA = rp & 3;
    const int growA = gateA * HH + cta * 4 + hofA;      // row rp
    const int growB = growA + 2 * HH;                    // row rp+8

    // preload W_hh slices, packed {w,w}
    ull w2a[16], w2b[16];
#pragma unroll
    for (int q = 0; q < 4; q++) {
        float4 wa = *(const float4*)(Whh + (size_t)growA * HH + kc * 16 + q * 4);
        float4 wb = *(const float4*)(Whh + (size_t)growB * HH + kc * 16 + q * 4);
        w2a[q * 4 + 0] = pack2(wa.x, wa.x); w2a[q * 4 + 1] = pack2(wa.y, wa.y);
        w2a[q * 4 + 2] = pack2(wa.z, wa.z); w2a[q * 4 + 3] = pack2(wa.w, wa.w);
        w2b[q * 4 + 0] = pack2(wb.x, wb.x); w2b[q * 4 + 1] = pack2(wb.y, wb.y);
        w2b[q * 4 + 2] = pack2(wb.z, wb.z); w2b[q * 4 + 3] = pack2(wb.w, wb.w);
    }

    // updater state (threads 0..127): (ub = batch, uh = h unit 0..3)
    const int ub = tid & 31, uh = tid >> 5;
    int   len = 0;
    float c_r = 0.0f, h_r = 0.0f;
    if (tid < 128) len = lengths[ub];

    for (int t = 0; t < TT; t++) {
        const int p = t & 1;
        // ---- stage h[k][b] -> swizzled smem; chunk c goes to ((c + (k>>4)) & 7)
        const float* hsrc = g_hbuf[p];
#pragma unroll
        for (int i = 0; i < 16; i++) {
            int fq = tid + i * 256;          // float4 index 0..4095
            int k = fq >> 3, c = fq & 7;
            float4 v = *(const float4*)(hsrc + (size_t)fq * 4);
            int chunk = (c + (k >> 4)) & 7;
            *(float4*)(h_s + k * 32 + chunk * 4) = v;
        }
        // prefetch this step's x_proj gates (consumed after the matmul)
        float xg0 = 0.f, xg1 = 0.f, xg2 = 0.f, xg3 = 0.f;
        if (tid < 128) {
            const float* xp = g_xp + ((size_t)t * GG + cta * 4 + uh) * BB + ub;
            xg0 = xp[0 * HH * BB];
            xg1 = xp[1 * HH * BB];
            xg2 = xp[2 * HH * BB];
            xg3 = xp[3 * HH * BB];
        }
        __syncthreads();

        // ---- matmul: partial dots over this thread's 16 k, 2 rows, 32 b
        ull accA[16], accB[16];
#pragma unroll
        for (int i = 0; i < 16; i++) { accA[i] = 0ull; accB[i] = 0ull; }
        const int sw = kc & 7;
#pragma unroll 4
        for (int j = 0; j < 16; j++) {
            const float* hrow = h_s + (kc * 16 + j) * 32;
            ull wa = w2a[j], wb = w2b[j];
#pragma unroll
            for (int c = 0; c < 8; c++) {
                int chunk = (c + sw) & 7;
                ulonglong2 hv = *(const ulonglong2*)(hrow + chunk * 4);
                accA[2 * c]     = ffma2(hv.x, wa, accA[2 * c]);
                accA[2 * c + 1] = ffma2(hv.y, wa, accA[2 * c + 1]);
                accB[2 * c]     = ffma2(hv.x, wb, accB[2 * c]);
                accB[2 * c + 1] = ffma2(hv.y, wb, accB[2 * c + 1]);
            }
        }
        // ---- write partials (ull stores, 2-ish way conflicts only)
        {
            ull* rA = (ull*)(red + (size_t)(kc * 16 + rp) * RED_PITCH);
            ull* rB = (ull*)(red + (size_t)(kc * 16 + rp + 8) * RED_PITCH);
#pragma unroll
            for (int i = 0; i < 16; i++) { rA[i] = accA[i]; rB[i] = accB[i]; }
        }
        __syncthreads();

        // ---- updaters: reduce over 32 k-chunks, apply gates
        if (tid < 128) {
            float v[4];
#pragma unroll
            for (int gt = 0; gt < 4; gt++) {
                int row = gt * 4 + uh;
                float s0 = 0.f, s1 = 0.f, s2 = 0.f, s3 = 0.f;
#pragma unroll
                for (int q = 0; q < 8; q++) {
                    s0 += red[((q * 4 + 0) * 16 + row) * RED_PITCH + ub];
                    s1 += red[((q * 4 + 1) * 16 + row) * RED_PITCH + ub];
                    s2 += red[((q * 4 + 2) * 16 + row) * RED_PITCH + ub];
                    s3 += red[((q * 4 + 3) * 16 + row) * RED_PITCH + ub];
                }
                v[gt] = (s0 + s1) + (s2 + s3);
            }
            float gi_ = sigm(xg0 + v[0]);
            float gf  = sigm(xg1 + v[1]);
            float gg  = tanhf(xg2 + v[2]);
            float go  = sigm(xg3 + v[3]);
            float c_new = gf * c_r + gi_ * gg;
            float h_new = go * tanhf(c_new);
            bool valid = (t < len);
            if (valid) { c_r = c_new; h_r = h_new; }
            ho[ub * 4 + uh] = valid ? h_new : 0.0f;
            g_hbuf[1 - p][(cta * 4 + uh) * BB + ub] = h_r;   // frozen past length
        }
        gridbar((unsigned)(t + 1));   // h buffer for t+1 globally visible

        // ---- coalesced output store: out[t][b][cta*4 .. cta*4+3]
        if (tid < 32) {
            float4 o4 = *(const float4*)(ho + tid * 4);
            *(float4*)(out + ((size_t)t * BB + tid) * HH + cta * 4) = o4;
        }
    }

    // final hT, cT
    if (tid < 128) {
        size_t base = (size_t)TT * BB * HH;
        out[base + (size_t)ub * HH + cta * 4 + uh] = h_r;
        out[base + (size_t)BB * HH + (size_t)ub * HH + cta * 4 + uh] = c_r;
    }
}

// =========================================================================
extern "C" void kernel_launch(void* const* d_in, const int* in_sizes, int n_in,
                              void* d_out, int out_size) {
    const float* src  = (const float*)d_in[0];
    const int*   lens = (const int*)d_in[1];
    const float* Wih  = (const float*)d_in[2];
    const float* Whh  = (const float*)d_in[3];
    const float* bih  = (const float*)d_in[4];
    const float* bhh  = (const float*)d_in[5];
    float* out = (float*)d_out;

    const int smem_xproj = (256 * WPITCH + 64 * XPITCH) * 4;
    const int smem_lstm  = (HH * BB + 32 * 16 * RED_PITCH + 128) * 4;
    cudaFuncSetAttribute(xproj_kernel, cudaFuncAttributeMaxDynamicSharedMemorySize, smem_xproj);
    cudaFuncSetAttribute(lstm_kernel,  cudaFuncAttributeMaxDynamicSharedMemorySize, smem_lstm);

    init_kernel<<<64, 256>>>();
    dim3 grid(8, 256);
    xproj_kernel<<<grid, 512, smem_xproj>>>(src, Wih, bih, bhh);
    lstm_kernel<<<NCTA, 256, smem_lstm>>>(lens, Whh, out);
}